// round 2
// baseline (speedup 1.0000x reference)
#include <cuda_runtime.h>

// Problem-fixed sizes (from setup_inputs)
#define BATCH 8
#define NH 778      // hand verts
#define FH 1538     // hand faces
#define NO 2000     // obj verts
#define FO 4000     // obj faces

#define TOLF    1e-7f
#define DETEPS  1e-8f   // float32(0.1 * TOL)
#define THRESH  25.0f

// Fixed ray direction (float32 of reference constants)
#define RDX 0.4395064455f
#define RDY 0.617598629942f
#define RDZ 0.652231566745f

struct __align__(16) Tri {
    float v0x, v0y, v0z, e1x;
    float e1y, e1z, e2x, e2y;
    float e2z, pvx, pvy, pvz;
    float inv, p0, p1, p2;
};

// Scratch (no allocations allowed)
__device__ Tri   d_htri[BATCH * FH];
__device__ Tri   d_otri[BATCH * FO];
__device__ int   d_hits_o[BATCH * NO];   // obj points vs hand tris
__device__ int   d_hits_h[BATCH * NH];   // hand points vs obj tris
__device__ float d_val_h[BATCH * NH];    // 25*tanh(anchor/25) per hand vert
__device__ float d_val_o[BATCH * NO];    // per obj vert (0 if invalid)
__device__ float d_part[BATCH * 6];      // per-batch {s_missed,c_missed,s_ph,c_ph,s_po,c_po}

// ---------------------------------------------------------------------------
__global__ void zero_kernel() {
    int i = blockIdx.x * blockDim.x + threadIdx.x;
    if (i < BATCH * NO) d_hits_o[i] = 0;
    if (i < BATCH * NH) d_hits_h[i] = 0;
    if (i < BATCH * 6)  d_part[i] = 0.0f;
}

// ---------------------------------------------------------------------------
// Precompute triangle invariants. invdet = 0 encodes (parallel || !valid),
// which makes u = v = t = 0 later and fails the u>0 test -> no hit,
// identical to the reference mask.
__device__ __forceinline__ void prep_body(const float* __restrict__ verts,
                                          const int* __restrict__ faces,
                                          const int* __restrict__ splits,
                                          int T, int NV, Tri* __restrict__ out) {
    int t = blockIdx.x * blockDim.x + threadIdx.x;
    if (t >= BATCH * T) return;
    int b = t / T, f = t - b * T;
    const int* fc = faces + (size_t)t * 3;
    const float* vb = verts + (size_t)b * NV * 3;
    int i0 = fc[0], i1 = fc[1], i2 = fc[2];
    float v0x = vb[i0*3+0], v0y = vb[i0*3+1], v0z = vb[i0*3+2];
    float v1x = vb[i1*3+0], v1y = vb[i1*3+1], v1z = vb[i1*3+2];
    float v2x = vb[i2*3+0], v2y = vb[i2*3+1], v2z = vb[i2*3+2];
    float e1x = v1x - v0x, e1y = v1y - v0y, e1z = v1z - v0z;
    float e2x = v2x - v0x, e2y = v2y - v0y, e2z = v2z - v0z;
    // pvec = RAY x e2
    float pvx = RDY * e2z - RDZ * e2y;
    float pvy = RDZ * e2x - RDX * e2z;
    float pvz = RDX * e2y - RDY * e2x;
    float det = e1x * pvx + e1y * pvy + e1z * pvz;
    bool ok = fabsf(det) >= TOLF;
    if (splits) ok = ok && (f < splits[b]);
    float inv = ok ? 1.0f / (det + DETEPS) : 0.0f;
    Tri tr;
    tr.v0x=v0x; tr.v0y=v0y; tr.v0z=v0z; tr.e1x=e1x;
    tr.e1y=e1y; tr.e1z=e1z; tr.e2x=e2x; tr.e2y=e2y;
    tr.e2z=e2z; tr.pvx=pvx; tr.pvy=pvy; tr.pvz=pvz;
    tr.inv=inv; tr.p0=0.f; tr.p1=0.f; tr.p2=0.f;
    out[t] = tr;
}

__global__ void prep_hand(const float* verts, const int* faces) {
    prep_body(verts, faces, nullptr, FH, NH, d_htri);
}
__global__ void prep_obj(const float* verts, const int* faces, const int* fsplits) {
    prep_body(verts, faces, fsplits, FO, NO, d_otri);
}

// ---------------------------------------------------------------------------
// Moller-Trumbore parity raycast. Split-K over triangles (blockIdx.y),
// partial hit counts accumulated with atomicAdd.
__device__ __forceinline__ void raycast_body(const float* __restrict__ pts, int P,
                                             const Tri* __restrict__ tris, int T,
                                             int tchunk, int* __restrict__ hits) {
    __shared__ Tri s[128];
    int b = blockIdx.z;
    int p = blockIdx.x * 128 + threadIdx.x;
    bool act = p < P;
    float px = 0.f, py = 0.f, pz = 0.f;
    if (act) {
        const float* pp = pts + ((size_t)b * P + p) * 3;
        px = pp[0]; py = pp[1]; pz = pp[2];
    }
    int t0 = blockIdx.y * tchunk;
    int t1 = min(t0 + tchunk, T);
    const Tri* tb = tris + (size_t)b * T;
    int cnt = 0;
    for (int base = t0; base < t1; base += 128) {
        int n = min(128, t1 - base);
        if (threadIdx.x < n) {
            const float4* src = (const float4*)&tb[base + threadIdx.x];
            float4* dst = (float4*)&s[threadIdx.x];
            dst[0] = src[0]; dst[1] = src[1]; dst[2] = src[2]; dst[3] = src[3];
        }
        __syncthreads();
        if (act) {
            #pragma unroll 4
            for (int j = 0; j < n; j++) {
                const float4* t4 = (const float4*)&s[j];
                float4 A = t4[0], Bq = t4[1], C = t4[2], D = t4[3];
                float inv = D.x;
                if (inv == 0.0f) continue;   // warp-uniform skip
                float tvx = px - A.x, tvy = py - A.y, tvz = pz - A.z;
                // u = dot(tvec, pvec) * inv
                float u = (tvx * C.y + tvy * C.z + tvz * C.w) * inv;
                // qvec = tvec x e1   (e1 = A.w, Bq.x, Bq.y)
                float qx = tvy * Bq.y - tvz * Bq.x;
                float qy = tvz * A.w  - tvx * Bq.y;
                float qz = tvx * Bq.x - tvy * A.w;
                float v = (qx * RDX + qy * RDY + qz * RDZ) * inv;
                // t = dot(e2, qvec)  (e2 = Bq.z, Bq.w, C.x)
                float tt = (Bq.z * qx + Bq.w * qy + C.x * qz) * inv;
                bool hit = (u > 0.f) && (u < 1.f) && (v > 0.f) &&
                           ((u + v) < 1.f) && (tt > TOLF);
                cnt += hit ? 1 : 0;
            }
        }
        __syncthreads();
    }
    if (act && cnt) atomicAdd(&hits[b * P + p], cnt);
}

__global__ void raycast_obj(const float* obj_verts, int tchunk) {
    raycast_body(obj_verts, NO, d_htri, FH, tchunk, d_hits_o);
}
__global__ void raycast_hand(const float* hand_verts, int tchunk) {
    raycast_body(hand_verts, NH, d_otri, FO, tchunk, d_hits_h);
}

// ---------------------------------------------------------------------------
// Nearest valid obj vert for each hand vert -> contact/collision value.
__global__ void closest_hand(const float* __restrict__ hv,
                             const float* __restrict__ ov,
                             const int* __restrict__ vsplit) {
    __shared__ float4 so[128];
    int b = blockIdx.y;
    int n = blockIdx.x * 128 + threadIdx.x;
    bool act = n < NH;
    float hx = 0.f, hy = 0.f, hz = 0.f, rx = 0.f;
    if (act) {
        const float* h = hv + ((size_t)b * NH + n) * 3;
        hx = h[0]; hy = h[1]; hz = h[2];
        rx = hx * hx + hy * hy + hz * hz;
    }
    int S = vsplit[b];
    float best = 3.4e38f; int bi = 0;
    for (int base = 0; base < S; base += 128) {
        int cnt = min(128, S - base);
        if (threadIdx.x < cnt) {
            const float* o = ov + ((size_t)b * NO + base + threadIdx.x) * 3;
            float ox = o[0], oy = o[1], oz = o[2];
            so[threadIdx.x] = make_float4(ox, oy, oz, ox*ox + oy*oy + oz*oz);
        }
        __syncthreads();
        if (act) {
            for (int j = 0; j < cnt; j++) {
                float4 o = so[j];
                float zz = hx * o.x + hy * o.y + hz * o.z;
                float d = rx + o.w - 2.0f * zz;
                if (d < best) { best = d; bi = base + j; }
            }
        }
        __syncthreads();
    }
    if (act) {
        const float* o = ov + ((size_t)b * NO + bi) * 3;
        float dx = o[0] - hx, dy = o[1] - hy, dz = o[2] - hz;
        float a = sqrtf(dx*dx + dy*dy + dz*dz);
        d_val_h[b * NH + n] = THRESH * tanhf(a / THRESH);
    }
}

// Nearest hand vert for each obj vert -> collision value (0 if invalid).
__global__ void closest_obj(const float* __restrict__ hv,
                            const float* __restrict__ ov,
                            const int* __restrict__ vsplit) {
    __shared__ float4 sh4[128];
    int b = blockIdx.y;
    int m = blockIdx.x * 128 + threadIdx.x;
    bool act = m < NO;
    int S = vsplit[b];
    bool valid = act && (m < S);
    float ox = 0.f, oy = 0.f, oz = 0.f, ry = 0.f;
    if (valid) {
        const float* o = ov + ((size_t)b * NO + m) * 3;
        ox = o[0]; oy = o[1]; oz = o[2];
        ry = ox*ox + oy*oy + oz*oz;
    }
    float best = 3.4e38f; int bi = 0;
    for (int base = 0; base < NH; base += 128) {
        int cnt = min(128, NH - base);
        if (threadIdx.x < cnt) {
            const float* h = hv + ((size_t)b * NH + base + threadIdx.x) * 3;
            float hx = h[0], hy = h[1], hz = h[2];
            sh4[threadIdx.x] = make_float4(hx, hy, hz, hx*hx + hy*hy + hz*hz);
        }
        __syncthreads();
        if (valid) {
            for (int j = 0; j < cnt; j++) {
                float4 h = sh4[j];
                float zz = h.x * ox + h.y * oy + h.z * oz;
                float d = h.w + ry - 2.0f * zz;
                if (d < best) { best = d; bi = base + j; }
            }
        }
        __syncthreads();
    }
    if (act) {
        float val = 0.0f;
        if (valid) {
            const float* h = hv + ((size_t)b * NH + bi) * 3;
            float dx = h[0] - ox, dy = h[1] - oy, dz = h[2] - oz;
            float a = sqrtf(dx*dx + dy*dy + dz*dz);
            val = THRESH * tanhf(a / THRESH);
        }
        d_val_o[b * NO + m] = val;
    }
}

// ---------------------------------------------------------------------------
__global__ void reduce_batch(const int* __restrict__ vsplit) {
    int b = blockIdx.x;
    float s1 = 0, c1 = 0, s2 = 0, c2 = 0, s3 = 0, c3 = 0;
    for (int n = threadIdx.x; n < NH; n += blockDim.x) {
        float v = d_val_h[b * NH + n];
        bool ext = (d_hits_h[b * NH + n] & 1) == 0;
        if (ext) { s1 += v; c1 += 1.f; }   // missed (exterior_hand)
        else     { s2 += v; c2 += 1.f; }   // penetr_h
    }
    int S = vsplit[b];
    for (int m = threadIdx.x; m < NO; m += blockDim.x) {
        if (m < S) {
            bool ext = (d_hits_o[b * NO + m] & 1) == 0;
            if (!ext) { s3 += d_val_o[b * NO + m]; c3 += 1.f; }
        }
    }
    // warp reduce then atomic to d_part
    #pragma unroll
    for (int off = 16; off; off >>= 1) {
        s1 += __shfl_down_sync(0xffffffffu, s1, off);
        c1 += __shfl_down_sync(0xffffffffu, c1, off);
        s2 += __shfl_down_sync(0xffffffffu, s2, off);
        c2 += __shfl_down_sync(0xffffffffu, c2, off);
        s3 += __shfl_down_sync(0xffffffffu, s3, off);
        c3 += __shfl_down_sync(0xffffffffu, c3, off);
    }
    if ((threadIdx.x & 31) == 0) {
        atomicAdd(&d_part[b*6+0], s1);
        atomicAdd(&d_part[b*6+1], c1);
        atomicAdd(&d_part[b*6+2], s2);
        atomicAdd(&d_part[b*6+3], c2);
        atomicAdd(&d_part[b*6+4], s3);
        atomicAdd(&d_part[b*6+5], c3);
    }
}

__global__ void finalize(float* __restrict__ out) {
    if (threadIdx.x != 0) return;
    float Sm = 0, Cm = 0, Sh = 0, Ch = 0, So = 0, Co = 0;
    for (int b = 0; b < BATCH; b++) {
        float s1 = d_part[b*6+0], c1 = d_part[b*6+1];
        float s2 = d_part[b*6+2], c2 = d_part[b*6+3];
        float s3 = d_part[b*6+4], c3 = d_part[b*6+5];
        Sm += s1; Cm += c1; Sh += s2; Ch += c2; So += s3; Co += c3;
        float missed_b = (c1 > 0.f) ? s1 / fmaxf(c1, 1.0f) : 0.0f;
        float ph_b     = (c2 > 0.f) ? s2 / fmaxf(c2, 1.0f) : 0.0f;
        float po_b     = (c3 > 0.f) ? s3 / fmaxf(c3, 1.0f) : 0.0f;
        out[2 + b]  = missed_b;
        out[10 + b] = ph_b + po_b;
    }
    float missed_loss = (Cm > 0.f) ? Sm / fmaxf(Cm, 1.0f) : 0.0f;
    float ph_loss     = (Ch > 0.f) ? Sh / fmaxf(Ch, 1.0f) : 0.0f;
    float po_loss     = (Co > 0.f) ? So / fmaxf(Co, 1.0f) : 0.0f;
    out[0] = missed_loss;
    out[1] = ph_loss + po_loss;
}

// ---------------------------------------------------------------------------
extern "C" void kernel_launch(void* const* d_in, const int* in_sizes, int n_in,
                              void* d_out, int out_size) {
    const float* hand_verts = (const float*)d_in[0];
    const int*   hand_faces = (const int*)d_in[1];
    const float* obj_verts  = (const float*)d_in[2];
    const int*   obj_faces  = (const int*)d_in[3];
    const int*   vsplits    = (const int*)d_in[4];
    const int*   fsplits    = (const int*)d_in[5];
    float* out = (float*)d_out;

    zero_kernel<<<(BATCH*NO + 255) / 256, 256>>>();

    prep_hand<<<(BATCH*FH + 127) / 128, 128>>>(hand_verts, hand_faces);
    prep_obj<<<(BATCH*FO + 127) / 128, 128>>>(obj_verts, obj_faces, fsplits);

    // obj points vs hand tris: 16 point-chunks x 4 tri-chunks x 8 batches
    raycast_obj<<<dim3((NO + 127) / 128, 4, BATCH), 128>>>(obj_verts, (FH + 3) / 4);
    // hand points vs obj tris: 7 point-chunks x 8 tri-chunks x 8 batches
    raycast_hand<<<dim3((NH + 127) / 128, 8, BATCH), 128>>>(hand_verts, FO / 8);

    closest_hand<<<dim3((NH + 127) / 128, BATCH), 128>>>(hand_verts, obj_verts, vsplits);
    closest_obj<<<dim3((NO + 127) / 128, BATCH), 128>>>(hand_verts, obj_verts, vsplits);

    reduce_batch<<<BATCH, 256>>>(vsplits);
    finalize<<<1, 32>>>(out);
}

// round 6
// speedup vs baseline: 2.0748x; 2.0748x over previous
#include <cuda_runtime.h>

// Problem-fixed sizes (from setup_inputs)
#define BATCH 8
#define NH 778      // hand verts
#define FH 1538     // hand faces
#define NO 2000     // obj verts
#define FO 4000     // obj faces

#define TOLF    1e-7f
#define DETEPS  1e-8f   // float32(0.1 * TOL)
#define THRESH  25.0f

// Fixed ray direction (float32 of reference constants)
#define RDX 0.4395064455f
#define RDY 0.617598629942f
#define RDZ 0.652231566745f

// Raycast tiling
#define PT   4            // points per thread (register tile)
#define RTPB 128          // threads per raycast block
#define PPB  (PT*RTPB)    // 512 points per block
#define TCH  128          // triangles per block (one smem stage)
#define PB_O ((NO + PPB - 1) / PPB)   // 4
#define PB_H ((NH + PPB - 1) / PPB)   // 2
#define TB_O ((FH + TCH - 1) / TCH)   // 13
#define TB_H ((FO + TCH - 1) / TCH)   // 32
#define BLKS_O (BATCH * PB_O * TB_O)  // 416
#define BLKS_H (BATCH * PB_H * TB_H)  // 512

// Closest-point tiling (split-K with atomic argmin)
#define SKO 4                         // chunks over obj dim (hand queries)
#define SKH 2                         // chunks over hand dim (obj queries)
#define QB_H ((NH + 127) / 128)       // 7
#define QB_O ((NO + 127) / 128)       // 16
#define OCH ((NO + SKO - 1) / SKO)    // 500
#define HCH ((NH + SKH - 1) / SKH)    // 389
#define CBLK_A (BATCH * QB_H * SKO)   // 224
#define CBLK_B (BATCH * QB_O * SKH)   // 256

// Scratch (no allocations allowed)
// Triangle affine forms: 3x float4 per triangle:
//  q0 = (nu.xyz, cu)  u = p.nu - cu
//  q1 = (nv.xyz, cv)  v = p.nv - cv
//  q2 = (nt.xyz, ct)  t = p.nt - ct
__device__ float4 d_htri[BATCH * FH * 3];
__device__ float4 d_otri[BATCH * FO * 3];
__device__ int    d_hits_o[BATCH * NO];
__device__ int    d_hits_h[BATCH * NH];
__device__ unsigned long long d_best_h[BATCH * NH];  // packed (distkey<<32)|idx
__device__ unsigned long long d_best_o[BATCH * NO];
__device__ float  d_val_h[BATCH * NH];
__device__ float  d_val_o[BATCH * NO];
__device__ float  d_part[BATCH * 6];

// ---------------------------------------------------------------------------
__global__ void zero_kernel() {
    int i = blockIdx.x * blockDim.x + threadIdx.x;
    if (i < BATCH * NO) { d_hits_o[i] = 0; d_best_o[i] = ~0ull; }
    if (i < BATCH * NH) { d_hits_h[i] = 0; d_best_h[i] = ~0ull; }
    if (i < BATCH * 6)  d_part[i] = 0.0f;
}

// ---------------------------------------------------------------------------
// Precompute triangle affine forms. invalid/parallel -> all-zero coefficients
// -> u=v=t=0 -> no hit (identical to the reference mask).
__global__ void prep_fused(const float* __restrict__ hv, const int* __restrict__ hf,
                           const float* __restrict__ ov, const int* __restrict__ of,
                           const int* __restrict__ fsplits) {
    int i = blockIdx.x * blockDim.x + threadIdx.x;
    const float* verts; const int* faces; float4* out;
    bool extra_valid = true;
    if (i < BATCH * FH) {
        int b = i / FH;
        verts = hv + (size_t)b * NH * 3;
        faces = hf + (size_t)i * 3;
        out   = d_htri + (size_t)i * 3;
    } else {
        int j = i - BATCH * FH;
        if (j >= BATCH * FO) return;
        int b = j / FO, f = j - b * FO;
        verts = ov + (size_t)b * NO * 3;
        faces = of + (size_t)j * 3;
        out   = d_otri + (size_t)j * 3;
        extra_valid = (f < fsplits[b]);
    }
    int i0 = faces[0], i1 = faces[1], i2 = faces[2];
    float v0x = verts[i0*3+0], v0y = verts[i0*3+1], v0z = verts[i0*3+2];
    float v1x = verts[i1*3+0], v1y = verts[i1*3+1], v1z = verts[i1*3+2];
    float v2x = verts[i2*3+0], v2y = verts[i2*3+1], v2z = verts[i2*3+2];
    float e1x = v1x - v0x, e1y = v1y - v0y, e1z = v1z - v0z;
    float e2x = v2x - v0x, e2y = v2y - v0y, e2z = v2z - v0z;
    // pvec = RAY x e2
    float pvx = RDY * e2z - RDZ * e2y;
    float pvy = RDZ * e2x - RDX * e2z;
    float pvz = RDX * e2y - RDY * e2x;
    float det = e1x * pvx + e1y * pvy + e1z * pvz;
    bool ok = (fabsf(det) >= TOLF) && extra_valid;
    float inv = ok ? 1.0f / (det + DETEPS) : 0.0f;
    // u = dot(p - v0, pvec)*inv = p.(pvec*inv) - v0.(pvec*inv)
    float nux = pvx * inv, nuy = pvy * inv, nuz = pvz * inv;
    float cu = v0x * nux + v0y * nuy + v0z * nuz;
    // v = dot((p-v0) x e1, RAY)*inv = (p-v0).(e1 x RAY)*inv
    float wx = e1y * RDZ - e1z * RDY;
    float wy = e1z * RDX - e1x * RDZ;
    float wz = e1x * RDY - e1y * RDX;
    float nvx = wx * inv, nvy = wy * inv, nvz = wz * inv;
    float cv = v0x * nvx + v0y * nvy + v0z * nvz;
    // t = dot(e2, (p-v0) x e1)*inv = (p-v0).(e1 x e2)*inv
    float gx = e1y * e2z - e1z * e2y;
    float gy = e1z * e2x - e1x * e2z;
    float gz = e1x * e2y - e1y * e2x;
    float ntx = gx * inv, nty = gy * inv, ntz = gz * inv;
    float ct = v0x * ntx + v0y * nty + v0z * ntz;
    out[0] = make_float4(nux, nuy, nuz, cu);
    out[1] = make_float4(nvx, nvy, nvz, cv);
    out[2] = make_float4(ntx, nty, ntz, ct);
}

// ---------------------------------------------------------------------------
// Fused parity raycast: obj-vs-hand-tris and hand-vs-obj-tris in one grid.
// 4 points per thread, one 128-triangle smem stage per block.
__global__ __launch_bounds__(RTPB, 8) void raycast_fused(
        const float* __restrict__ hv, const float* __restrict__ ov,
        const int* __restrict__ fsplits) {
    __shared__ float4 s[TCH * 3];
    int bid = blockIdx.x;
    const float* pts; const float4* tb; int* hits;
    int P, t0, t1, pofs;
    if (bid < BLKS_O) {
        int b = bid / (PB_O * TB_O);
        int r = bid - b * (PB_O * TB_O);
        int pblk = r / TB_O, tcb = r - pblk * TB_O;
        pts  = ov + (size_t)b * NO * 3;  P = NO;
        tb   = d_htri + (size_t)b * FH * 3;
        hits = d_hits_o + b * NO;
        t0 = tcb * TCH; t1 = min(t0 + TCH, FH);
        pofs = pblk * PPB;
    } else {
        int r2 = bid - BLKS_O;
        int b = r2 / (PB_H * TB_H);
        int r = r2 - b * (PB_H * TB_H);
        int pblk = r / TB_H, tcb = r - pblk * TB_H;
        pts  = hv + (size_t)b * NH * 3;  P = NH;
        tb   = d_otri + (size_t)b * FO * 3;
        hits = d_hits_h + b * NH;
        int lim = fsplits[b];                     // invalid tail is contiguous
        t0 = tcb * TCH; t1 = min(t0 + TCH, lim);
        pofs = pblk * PPB;
        if (t0 >= t1) return;                     // block-uniform early out
    }

    float px[PT], py[PT], pz[PT];
    int cnt[PT];
    bool act[PT];
    #pragma unroll
    for (int k = 0; k < PT; k++) {
        int p = pofs + k * RTPB + threadIdx.x;
        act[k] = p < P;
        int pc = act[k] ? p : 0;
        px[k] = pts[pc*3+0]; py[k] = pts[pc*3+1]; pz[k] = pts[pc*3+2];
        cnt[k] = 0;
    }

    int n = t1 - t0;
    if (threadIdx.x < n) {
        const float4* src = tb + (size_t)(t0 + threadIdx.x) * 3;
        s[threadIdx.x*3+0] = src[0];
        s[threadIdx.x*3+1] = src[1];
        s[threadIdx.x*3+2] = src[2];
    }
    __syncthreads();

    for (int j = 0; j < n; j++) {
        float4 q0 = s[j*3+0], q1 = s[j*3+1], q2 = s[j*3+2];
        #pragma unroll
        for (int k = 0; k < PT; k++) {
            float u = fmaf(pz[k], q0.z, fmaf(py[k], q0.y, fmaf(px[k], q0.x, -q0.w)));
            float v = fmaf(pz[k], q1.z, fmaf(py[k], q1.y, fmaf(px[k], q1.x, -q1.w)));
            float t = fmaf(pz[k], q2.z, fmaf(py[k], q2.y, fmaf(px[k], q2.x, -q2.w)));
            // u<1 is implied by (v>0 && u+v<1); invalid tris give u=v=t=0 -> miss
            bool hit = (fminf(u, v) > 0.0f) & ((u + v) < 1.0f) & (t > TOLF);
            cnt[k] += hit ? 1 : 0;
        }
    }
    #pragma unroll
    for (int k = 0; k < PT; k++) {
        if (act[k] && cnt[k])
            atomicAdd(&hits[pofs + k * RTPB + threadIdx.x], cnt[k]);
    }
}

// ---------------------------------------------------------------------------
// Split-K nearest neighbor, both directions, fused. Argmin via 64-bit
// atomicMin on (orderable-dist-bits << 32 | idx): ties -> lowest idx, which
// matches jnp.argmin first-occurrence semantics.
__device__ __forceinline__ unsigned long long pack_key(float d, int idx) {
    unsigned u = __float_as_uint(d);
    unsigned k32 = (u & 0x80000000u) ? ~u : (u | 0x80000000u);
    return ((unsigned long long)k32 << 32) | (unsigned)idx;
}

__global__ __launch_bounds__(128) void closest_fused(
        const float* __restrict__ hv, const float* __restrict__ ov,
        const int* __restrict__ vsplit) {
    __shared__ float4 tile[128];
    int bid = blockIdx.x;
    if (bid < CBLK_A) {
        // hand queries vs valid obj verts
        int b = bid / (QB_H * SKO);
        int r = bid - b * (QB_H * SKO);
        int qb = r / SKO, sk = r - qb * SKO;
        int S = vsplit[b];
        int c0 = sk * OCH, c1 = min(c0 + OCH, S);
        if (c0 >= c1) return;
        int n = qb * 128 + threadIdx.x;
        bool act = n < NH;
        float hx = 0.f, hy = 0.f, hz = 0.f, rx = 0.f;
        if (act) {
            const float* h = hv + ((size_t)b * NH + n) * 3;
            hx = h[0]; hy = h[1]; hz = h[2];
            rx = hx*hx + hy*hy + hz*hz;
        }
        float best = 3.4e38f; int bi = c0;
        for (int base = c0; base < c1; base += 128) {
            int cntn = min(128, c1 - base);
            if (threadIdx.x < cntn) {
                const float* o = ov + ((size_t)b * NO + base + threadIdx.x) * 3;
                float ox = o[0], oy = o[1], oz = o[2];
                tile[threadIdx.x] = make_float4(ox, oy, oz, ox*ox + oy*oy + oz*oz);
            }
            __syncthreads();
            if (act) {
                for (int j = 0; j < cntn; j++) {
                    float4 o = tile[j];
                    float zz = hx*o.x + hy*o.y + hz*o.z;
                    float d = rx + o.w - 2.0f * zz;
                    if (d < best) { best = d; bi = base + j; }
                }
            }
            __syncthreads();
        }
        if (act) atomicMin(&d_best_h[b * NH + n], pack_key(best, bi));
    } else {
        // obj queries vs hand verts
        int r2 = bid - CBLK_A;
        int b = r2 / (QB_O * SKH);
        int r = r2 - b * (QB_O * SKH);
        int qb = r / SKH, sk = r - qb * SKH;
        int c0 = sk * HCH, c1 = min(c0 + HCH, NH);
        int S = vsplit[b];
        int m = qb * 128 + threadIdx.x;
        bool valid = (m < NO) && (m < S);
        float ox = 0.f, oy = 0.f, oz = 0.f, ry = 0.f;
        if (valid) {
            const float* o = ov + ((size_t)b * NO + m) * 3;
            ox = o[0]; oy = o[1]; oz = o[2];
            ry = ox*ox + oy*oy + oz*oz;
        }
        float best = 3.4e38f; int bi = c0;
        for (int base = c0; base < c1; base += 128) {
            int cntn = min(128, c1 - base);
            if (threadIdx.x < cntn) {
                const float* h = hv + ((size_t)b * NH + base + threadIdx.x) * 3;
                float hx = h[0], hy = h[1], hz = h[2];
                tile[threadIdx.x] = make_float4(hx, hy, hz, hx*hx + hy*hy + hz*hz);
            }
            __syncthreads();
            if (valid) {
                for (int j = 0; j < cntn; j++) {
                    float4 h = tile[j];
                    float zz = h.x*ox + h.y*oy + h.z*oz;
                    float d = h.w + ry - 2.0f * zz;
                    if (d < best) { best = d; bi = base + j; }
                }
            }
            __syncthreads();
        }
        if (valid) atomicMin(&d_best_o[b * NO + m], pack_key(best, bi));
    }
}

// Resolve argmin -> anchor distance -> 25*tanh(d/25)
__global__ void values_kernel(const float* __restrict__ hv,
                              const float* __restrict__ ov,
                              const int* __restrict__ vsplit) {
    int i = blockIdx.x * blockDim.x + threadIdx.x;
    if (i < BATCH * NH) {
        int b = i / NH;
        int bi = (int)(d_best_h[i] & 0xffffffffu);
        const float* h = hv + (size_t)i * 3;
        const float* o = ov + ((size_t)b * NO + bi) * 3;
        float dx = o[0]-h[0], dy = o[1]-h[1], dz = o[2]-h[2];
        float a = sqrtf(dx*dx + dy*dy + dz*dz);
        d_val_h[i] = THRESH * tanhf(a / THRESH);
    }
    if (i < BATCH * NO) {
        int b = i / NO, m = i - b * NO;
        float val = 0.0f;
        if (m < vsplit[b]) {
            int bi = (int)(d_best_o[i] & 0xffffffffu);
            const float* o = ov + (size_t)i * 3;
            const float* h = hv + ((size_t)b * NH + bi) * 3;
            float dx = h[0]-o[0], dy = h[1]-o[1], dz = h[2]-o[2];
            float a = sqrtf(dx*dx + dy*dy + dz*dz);
            val = THRESH * tanhf(a / THRESH);
        }
        d_val_o[i] = val;
    }
}

// ---------------------------------------------------------------------------
__global__ void reduce_batch(const int* __restrict__ vsplit) {
    int b = blockIdx.x;
    float s1 = 0, c1 = 0, s2 = 0, c2 = 0, s3 = 0, c3 = 0;
    for (int n = threadIdx.x; n < NH; n += blockDim.x) {
        float v = d_val_h[b * NH + n];
        bool ext = (d_hits_h[b * NH + n] & 1) == 0;
        if (ext) { s1 += v; c1 += 1.f; }
        else     { s2 += v; c2 += 1.f; }
    }
    int S = vsplit[b];
    for (int m = threadIdx.x; m < NO; m += blockDim.x) {
        if (m < S) {
            bool ext = (d_hits_o[b * NO + m] & 1) == 0;
            if (!ext) { s3 += d_val_o[b * NO + m]; c3 += 1.f; }
        }
    }
    #pragma unroll
    for (int off = 16; off; off >>= 1) {
        s1 += __shfl_down_sync(0xffffffffu, s1, off);
        c1 += __shfl_down_sync(0xffffffffu, c1, off);
        s2 += __shfl_down_sync(0xffffffffu, s2, off);
        c2 += __shfl_down_sync(0xffffffffu, c2, off);
        s3 += __shfl_down_sync(0xffffffffu, s3, off);
        c3 += __shfl_down_sync(0xffffffffu, c3, off);
    }
    if ((threadIdx.x & 31) == 0) {
        atomicAdd(&d_part[b*6+0], s1);
        atomicAdd(&d_part[b*6+1], c1);
        atomicAdd(&d_part[b*6+2], s2);
        atomicAdd(&d_part[b*6+3], c2);
        atomicAdd(&d_part[b*6+4], s3);
        atomicAdd(&d_part[b*6+5], c3);
    }
}

__global__ void finalize(float* __restrict__ out) {
    if (threadIdx.x != 0) return;
    float Sm = 0, Cm = 0, Sh = 0, Ch = 0, So = 0, Co = 0;
    for (int b = 0; b < BATCH; b++) {
        float s1 = d_part[b*6+0], c1 = d_part[b*6+1];
        float s2 = d_part[b*6+2], c2 = d_part[b*6+3];
        float s3 = d_part[b*6+4], c3 = d_part[b*6+5];
        Sm += s1; Cm += c1; Sh += s2; Ch += c2; So += s3; Co += c3;
        float missed_b = (c1 > 0.f) ? s1 / fmaxf(c1, 1.0f) : 0.0f;
        float ph_b     = (c2 > 0.f) ? s2 / fmaxf(c2, 1.0f) : 0.0f;
        float po_b     = (c3 > 0.f) ? s3 / fmaxf(c3, 1.0f) : 0.0f;
        out[2 + b]  = missed_b;
        out[10 + b] = ph_b + po_b;
    }
    float missed_loss = (Cm > 0.f) ? Sm / fmaxf(Cm, 1.0f) : 0.0f;
    float ph_loss     = (Ch > 0.f) ? Sh / fmaxf(Ch, 1.0f) : 0.0f;
    float po_loss     = (Co > 0.f) ? So / fmaxf(Co, 1.0f) : 0.0f;
    out[0] = missed_loss;
    out[1] = ph_loss + po_loss;
}

// ---------------------------------------------------------------------------
extern "C" void kernel_launch(void* const* d_in, const int* in_sizes, int n_in,
                              void* d_out, int out_size) {
    const float* hand_verts = (const float*)d_in[0];
    const int*   hand_faces = (const int*)d_in[1];
    const float* obj_verts  = (const float*)d_in[2];
    const int*   obj_faces  = (const int*)d_in[3];
    const int*   vsplits    = (const int*)d_in[4];
    const int*   fsplits    = (const int*)d_in[5];
    float* out = (float*)d_out;

    zero_kernel<<<(BATCH * NO + 255) / 256, 256>>>();
    prep_fused<<<(BATCH * (FH + FO) + 127) / 128, 128>>>(
        hand_verts, hand_faces, obj_verts, obj_faces, fsplits);
    raycast_fused<<<BLKS_O + BLKS_H, RTPB>>>(hand_verts, obj_verts, fsplits);
    closest_fused<<<CBLK_A + CBLK_B, 128>>>(hand_verts, obj_verts, vsplits);
    values_kernel<<<(BATCH * NO + 127) / 128, 128>>>(hand_verts, obj_verts, vsplits);
    reduce_batch<<<BATCH, 256>>>(vsplits);
    finalize<<<1, 32>>>(out);
}